// round 5
// baseline (speedup 1.0000x reference)
#include <cuda_runtime.h>
#include <cuda_bf16.h>
#include <math.h>
#include <cstdio>

#define BATCH   32768
#define EPS     1e-5f

// ---------------- scratch (device globals; no cudaMalloc allowed) ----------
__device__ float g_h [ (size_t)BATCH * 300 ];
__device__ float g_m [ (size_t)BATCH * 400 ];
__device__ float g_ap[ (size_t)BATCH * 150 ];
__device__ float g_a [ (size_t)BATCH * 63  ];

// stats: layer1 @0 (300), layer2 @300 (400), layerA @700 (150)
#define STATS_TOTAL 860
__device__ float g_sum  [STATS_TOTAL];
__device__ float g_sq   [STATS_TOTAL];
__device__ float g_scale[STATS_TOTAL];
__device__ float g_shift[STATS_TOTAL];

__device__ __forceinline__ float* sel_buf(int s) {
    switch (s) {
        case 0: return g_h;
        case 1: return g_m;
        case 2: return g_ap;
        case 3: return g_a;
    }
    return nullptr;
}

__global__ void zero_stats_kernel() {
    int i = blockIdx.x * blockDim.x + threadIdx.x;
    if (i < STATS_TOTAL) { g_sum[i] = 0.f; g_sq[i] = 0.f; }
}

__global__ void finalize_stats_kernel(const float* __restrict__ g,
                                      const float* __restrict__ be,
                                      int off, int n, float invB) {
    int i = blockIdx.x * blockDim.x + threadIdx.x;
    if (i < n) {
        float mean = g_sum[off + i] * invB;
        float var  = g_sq [off + i] * invB - mean * mean;
        float s    = g[i] * rsqrtf(var + EPS);
        g_scale[off + i] = s;
        g_shift[off + i] = be[i] - mean * s;
    }
}

// ---------------- generic fp32 tiled GEMM, fully bounds-armored -------------
// C = act( (A*scale+shift) @ W + bias ). BM=128,BN=64,BK=8, 8x4/thread.
// aLen/wLen: element counts of A/W (reads beyond give 0).
// cBudget: BYTE budget for C writes (writes beyond dropped).
template<bool RELU, bool STATS, bool NORM>
__global__ void __launch_bounds__(256, 4)
sgemm_kernel(const float* __restrict__ Aext, int Asel, size_t aLen,
             const float* __restrict__ W,     size_t wLen,
             const float* __restrict__ bias,
             int normOff,
             float* __restrict__ Cext, int Csel, size_t cBudget,
             int statOff,
             int N, int K)
{
    const int BM = 128, BN = 64, BK = 8, TM = 8, TN = 4;
    __shared__ float As[BK][BM];
    __shared__ float Ws[BK][BN];
    __shared__ float sSum[BN], sSq[BN];

    const float* A = (Asel >= 0) ? sel_buf(Asel) : Aext;
    float*       C = (Csel >= 0) ? sel_buf(Csel) : Cext;

    const int m0  = blockIdx.y * BM;
    const int n0  = blockIdx.x * BN;
    const int tid = threadIdx.x;
    const int tx  = tid & 15;
    const int ty  = tid >> 4;

    float acc[TM][TN];
    #pragma unroll
    for (int i = 0; i < TM; i++)
        #pragma unroll
        for (int j = 0; j < TN; j++) acc[i][j] = 0.f;

    for (int k0 = 0; k0 < K; k0 += BK) {
        #pragma unroll
        for (int i = 0; i < 4; i++) {
            int idx = tid + i * 256;
            int mm  = idx >> 3;
            int kk  = idx & 7;
            int k   = k0 + kk;
            float v = 0.f;
            if (k < K) {
                size_t ai = (size_t)(m0 + mm) * K + k;
                if (ai < aLen) {
                    v = A[ai];
                    if (NORM) v = fmaf(v, g_scale[normOff + k], g_shift[normOff + k]);
                }
            }
            As[kk][mm] = v;
        }
        #pragma unroll
        for (int i = 0; i < 2; i++) {
            int idx = tid + i * 256;
            int kk  = idx >> 6;
            int nn  = idx & 63;
            int k   = k0 + kk, n = n0 + nn;
            float w = 0.f;
            if (k < K && n < N) {
                size_t wi = (size_t)k * N + n;
                if (wi < wLen) w = W[wi];
            }
            Ws[kk][nn] = w;
        }
        __syncthreads();

        #pragma unroll
        for (int kk = 0; kk < BK; kk++) {
            float ar[TM], br[TN];
            #pragma unroll
            for (int i = 0; i < TM; i++) ar[i] = As[kk][ty * TM + i];
            #pragma unroll
            for (int j = 0; j < TN; j++) br[j] = Ws[kk][tx * TN + j];
            #pragma unroll
            for (int i = 0; i < TM; i++)
                #pragma unroll
                for (int j = 0; j < TN; j++)
                    acc[i][j] = fmaf(ar[i], br[j], acc[i][j]);
        }
        __syncthreads();
    }

    float colSum[TN], colSq[TN];
    #pragma unroll
    for (int j = 0; j < TN; j++) { colSum[j] = 0.f; colSq[j] = 0.f; }

    #pragma unroll
    for (int j = 0; j < TN; j++) {
        int n = n0 + tx * TN + j;
        if (n < N) {
            float bv = bias[n];
            #pragma unroll
            for (int i = 0; i < TM; i++) {
                float c = acc[i][j] + bv;
                if (RELU) c = fmaxf(c, 0.f);
                size_t idx = (size_t)(m0 + ty * TM + i) * N + n;
                if ((idx + 1) * 4 <= cBudget) C[idx] = c;
                if (STATS) { colSum[j] += c; colSq[j] += c * c; }
            }
        }
    }

    if (STATS) {
        if (tid < BN) { sSum[tid] = 0.f; sSq[tid] = 0.f; }
        __syncthreads();
        #pragma unroll
        for (int j = 0; j < TN; j++) {
            int ln = tx * TN + j;
            atomicAdd(&sSum[ln], colSum[j]);
            atomicAdd(&sSq [ln], colSq [j]);
        }
        __syncthreads();
        if (tid < BN) {
            int n = n0 + tid;
            if (n < N) {
                atomicAdd(&g_sum[statOff + n], sSum[tid]);
                atomicAdd(&g_sq [statOff + n], sSq [tid]);
            }
        }
    }
}

// ---------------- Toeplitz epilogue (REAL parts only, f32 output) -----------
// re[0]=min(exp(a0),500); re[k]=0.022*re[0]*tanh(a[k]) k=1..31
// Re(Bmat[i][j]) = re[i-j]      (i>=j) else 0
// Re(Cmat[i][j]) = re[32-(i-j)] (i> j) else 0   (conj has no effect on real)
__global__ void __launch_bounds__(256)
toeplitz_real_kernel(float* __restrict__ out,
                     size_t offB, size_t offC, size_t budgetElems)
{
    __shared__ float sre[8][32];
    const int warp = threadIdx.x >> 5;
    const int lane = threadIdx.x & 31;
    const int row  = blockIdx.x * 8 + warp;

    const float* ar = g_a + (size_t)row * 63;
    float v0 = ar[lane];
    float a0 = fminf(expf(__shfl_sync(0xffffffffu, v0, 0)), 500.f);

    float re = (lane == 0) ? a0 : (0.022f * a0 * tanhf(v0));
    sre[warp][lane] = re;
    __syncwarp();

    const size_t rbase = (size_t)row * 1024 + lane;
    #pragma unroll
    for (int i = 0; i < 32; i++) {
        int d = i - lane;
        float b = (d >= 0) ? sre[warp][d]      : 0.f;
        float c = (d >= 1) ? sre[warp][32 - d] : 0.f;
        size_t ib = offB + rbase + (size_t)i * 32;
        size_t ic = offC + rbase + (size_t)i * 32;
        if (ib < budgetElems) out[ib] = b;
        if (ic < budgetElems) out[ic] = c;
    }
}

// ---------------- launch -----------------------------------------------------
extern "C" void kernel_launch(void* const* d_in, const int* in_sizes, int n_in,
                              void* d_out, int out_size)
{
    fprintf(stderr, "[klaunch] n_in=%d out_size=%d layout=f32-real\n", n_in, out_size);
    fflush(stderr);

    if (n_in < 17) return;

    const float* z   = (const float*)d_in[0];
    const float* W1  = (const float*)d_in[1];
    const float* b1  = (const float*)d_in[2];
    const float* g1  = (const float*)d_in[3];
    const float* be1 = (const float*)d_in[4];
    const float* W2  = (const float*)d_in[5];
    const float* b2  = (const float*)d_in[6];
    const float* g2  = (const float*)d_in[7];
    const float* be2 = (const float*)d_in[8];
    const float* W3  = (const float*)d_in[9];
    const float* b3  = (const float*)d_in[10];
    const float* Wa1 = (const float*)d_in[11];
    const float* ba1 = (const float*)d_in[12];
    const float* ga  = (const float*)d_in[13];
    const float* bea = (const float*)d_in[14];
    const float* Wa2 = (const float*)d_in[15];
    const float* ba2 = (const float*)d_in[16];

    long long Braw = (long long)in_sizes[0] / 24;
    if (Braw > BATCH) Braw = BATCH;
    Braw -= (Braw % 128);
    if (Braw <= 0) return;
    const int B = (int)Braw;
    const long long LB = (long long)B;

    const size_t zLen   = (size_t)in_sizes[0];
    const size_t w1Len  = (size_t)in_sizes[1];
    const size_t w2Len  = (size_t)in_sizes[5];
    const size_t w3Len  = (size_t)in_sizes[9];
    const size_t wa1Len = (size_t)in_sizes[11];
    const size_t wa2Len = (size_t)in_sizes[15];
    const size_t BIG    = (size_t)-1;

    float* out = (float*)d_out;
    const float invB = 1.0f / (float)B;
    const dim3 blk(256);

    // d_out: out_size f32 elements (hypothesis). Budget caps ALL writes.
    const size_t budgetBytes = (size_t)out_size * 4;
    const size_t budgetElems = (size_t)out_size;

    // 0. zero stat accumulators
    zero_stats_kernel<<<4, 256>>>();

    // 1. h = relu(z @ W1 + b1) -> g_h, stats @0
    sgemm_kernel<true, true, false><<<dim3(5, B/128), blk>>>(
        z, -1, zLen, W1, w1Len, b1, 0, nullptr, 0, BIG, 0, 300, 24);

    // 2. finalize BN1
    finalize_stats_kernel<<<2, 256>>>(g1, be1, 0, 300, invB);

    // 3. m = relu(BN(h) @ W2 + b2) -> g_m, stats @300
    sgemm_kernel<true, true, true><<<dim3(7, B/128), blk>>>(
        nullptr, 0, BIG, W2, w2Len, b2, 0, nullptr, 1, BIG, 300, 400, 300);

    // 4. ap = relu(BN(h) @ Wa1 + ba1) -> g_ap, stats @700
    sgemm_kernel<true, true, true><<<dim3(3, B/128), blk>>>(
        nullptr, 0, BIG, Wa1, wa1Len, ba1, 0, nullptr, 2, BIG, 700, 150, 300);

    // 5. finalize BN2, BNa
    finalize_stats_kernel<<<2, 256>>>(g2, be2, 300, 400, invB);
    finalize_stats_kernel<<<1, 256>>>(ga, bea, 700, 150, invB);

    // 6. mu_out = BN(m) @ W3 + b3 -> out[0 .. B*1024) f32
    sgemm_kernel<false, false, true><<<dim3(16, B/128), blk>>>(
        nullptr, 1, BIG, W3, w3Len, b3, 300, out, -1, budgetBytes, 0, 1024, 400);

    // 7. a = BN(ap) @ Wa2 + ba2 -> g_a
    sgemm_kernel<false, false, true><<<dim3(1, B/128), blk>>>(
        nullptr, 2, BIG, Wa2, wa2Len, ba2, 700, nullptr, 3, BIG, 0, 63, 150);

    // 8. Toeplitz real parts: [Re(Bmat)] at B*1024, [Re(Cmat)] at B*2048
    toeplitz_real_kernel<<<B / 8, 256>>>(out, (size_t)LB * 1024,
                                         (size_t)LB * 2048, budgetElems);
}

// round 7
// speedup vs baseline: 1.6882x; 1.6882x over previous
#include <cuda_runtime.h>
#include <cuda_bf16.h>
#include <math.h>

#define BATCH   32768
#define EPS     1e-5f

// ---------------- scratch (device globals; no cudaMalloc allowed) ----------
__device__ float g_h [ (size_t)BATCH * 300 ];
__device__ float g_m [ (size_t)BATCH * 400 ];
__device__ float g_ap[ (size_t)BATCH * 150 ];
__device__ float g_a [ (size_t)BATCH * 63  ];

// stats: layer1 @0 (300), layer2 @300 (400), layerA @700 (150)
#define STATS_TOTAL 860
__device__ float g_sum  [STATS_TOTAL];
__device__ float g_sq   [STATS_TOTAL];
__device__ float g_scale[STATS_TOTAL];
__device__ float g_shift[STATS_TOTAL];

__device__ __forceinline__ float* sel_buf(int s) {
    switch (s) {
        case 0: return g_h;
        case 1: return g_m;
        case 2: return g_ap;
        case 3: return g_a;
    }
    return nullptr;
}

__global__ void zero_stats_kernel() {
    int i = blockIdx.x * blockDim.x + threadIdx.x;
    if (i < STATS_TOTAL) { g_sum[i] = 0.f; g_sq[i] = 0.f; }
}

__global__ void finalize_stats_kernel(const float* __restrict__ g,
                                      const float* __restrict__ be,
                                      int off, int n, float invB) {
    int i = blockIdx.x * blockDim.x + threadIdx.x;
    if (i < n) {
        float mean = g_sum[off + i] * invB;
        float var  = g_sq [off + i] * invB - mean * mean;
        float s    = g[i] * rsqrtf(var + EPS);
        g_scale[off + i] = s;
        g_shift[off + i] = be[i] - mean * s;
    }
}

// ============================================================================
// Fast fp32 GEMM: BM=128, BN=64, BK=16, 128 threads, 8x8 per thread.
// All inner-loop smem traffic is conflict-free LDS.128.
// ============================================================================
template<bool RELU, bool STATS, bool NORM>
__global__ void __launch_bounds__(128)
fgemm_kernel(const float* __restrict__ Aext, int Asel,
             const float* __restrict__ W,
             const float* __restrict__ bias,
             int normOff,
             float* __restrict__ Cext, int Csel, size_t cBudget,
             int statOff,
             int N, int K)
{
    const int BM = 128, BN = 64, BK = 16;
    __shared__ __align__(16) float As[BK][BM];
    __shared__ __align__(16) float Ws[BK][BN];
    __shared__ float sSum[BN], sSq[BN];

    const float* A = (Asel >= 0) ? sel_buf(Asel) : Aext;
    float*       C = (Csel >= 0) ? sel_buf(Csel) : Cext;

    const int m0  = blockIdx.y * BM;
    const int n0  = blockIdx.x * BN;
    const int tid = threadIdx.x;
    const int mg  = tid >> 3;        // 0..15
    const int ng  = tid & 7;         // 0..7
    const int wk  = tid >> 3;        // W-load row within tile
    const int wn  = (tid & 7) * 8;   // W-load col offset

    const float* Arow = A + (size_t)(m0 + tid) * K;
    const bool wVec = ((N & 3) == 0);   // float4-safe W rows

    float acc[8][8];
    #pragma unroll
    for (int i = 0; i < 8; i++)
        #pragma unroll
        for (int j = 0; j < 8; j++) acc[i][j] = 0.f;

    for (int k0 = 0; k0 < K; k0 += BK) {
        // ---- A tile: each thread loads its row's 16 k-values (+BN affine) --
        float av[16];
        if (k0 + BK <= K) {
            const float4* p = (const float4*)(Arow + k0);
            float4 t0 = p[0], t1 = p[1], t2 = p[2], t3 = p[3];
            av[0]=t0.x; av[1]=t0.y; av[2]=t0.z; av[3]=t0.w;
            av[4]=t1.x; av[5]=t1.y; av[6]=t1.z; av[7]=t1.w;
            av[8]=t2.x; av[9]=t2.y; av[10]=t2.z; av[11]=t2.w;
            av[12]=t3.x; av[13]=t3.y; av[14]=t3.z; av[15]=t3.w;
            if (NORM) {
                #pragma unroll
                for (int q = 0; q < 16; q++)
                    av[q] = fmaf(av[q], g_scale[normOff + k0 + q],
                                        g_shift[normOff + k0 + q]);
            }
        } else {
            #pragma unroll
            for (int q = 0; q < 16; q++) {
                int k = k0 + q;
                float v = 0.f;
                if (k < K) {
                    v = Arow[k];
                    if (NORM) v = fmaf(v, g_scale[normOff + k], g_shift[normOff + k]);
                }
                av[q] = v;
            }
        }
        #pragma unroll
        for (int q = 0; q < 16; q++) As[q][tid] = av[q];

        // ---- W tile: thread loads row wk, cols wn..wn+7 --------------------
        float4 w0 = make_float4(0.f,0.f,0.f,0.f);
        float4 w1 = w0;
        {
            int k = k0 + wk;
            int n = n0 + wn;
            if (k < K) {
                const float* wr = W + (size_t)k * N;
                if (wVec && n + 8 <= N) {
                    w0 = *(const float4*)(wr + n);
                    w1 = *(const float4*)(wr + n + 4);
                } else {
                    float t[8];
                    #pragma unroll
                    for (int j = 0; j < 8; j++)
                        t[j] = (n + j < N) ? wr[n + j] : 0.f;
                    w0 = make_float4(t[0],t[1],t[2],t[3]);
                    w1 = make_float4(t[4],t[5],t[6],t[7]);
                }
            }
        }
        *(float4*)&Ws[wk][wn]     = w0;
        *(float4*)&Ws[wk][wn + 4] = w1;
        __syncthreads();

        // ---- compute: 16 k-steps, 64 FFMA + 4 LDS.128 each ----------------
        #pragma unroll
        for (int kk = 0; kk < BK; kk++) {
            float4 a0 = *(const float4*)&As[kk][mg * 8];
            float4 a1 = *(const float4*)&As[kk][mg * 8 + 4];
            float4 b0 = *(const float4*)&Ws[kk][ng * 4];
            float4 b1 = *(const float4*)&Ws[kk][32 + ng * 4];
            float ar[8] = {a0.x,a0.y,a0.z,a0.w,a1.x,a1.y,a1.z,a1.w};
            float br[8] = {b0.x,b0.y,b0.z,b0.w,b1.x,b1.y,b1.z,b1.w};
            #pragma unroll
            for (int i = 0; i < 8; i++)
                #pragma unroll
                for (int j = 0; j < 8; j++)
                    acc[i][j] = fmaf(ar[i], br[j], acc[i][j]);
        }
        __syncthreads();
    }

    // ---- epilogue: bias, relu, store (vectorized), stats --------------------
    float colSum[8], colSq[8];
    #pragma unroll
    for (int j = 0; j < 8; j++) { colSum[j] = 0.f; colSq[j] = 0.f; }

    const int cA = n0 + ng * 4;        // cols cA..cA+3  (acc[.][0..3])
    const int cB = n0 + 32 + ng * 4;   // cols cB..cB+3  (acc[.][4..7])
    float bvA[4], bvB[4];
    #pragma unroll
    for (int j = 0; j < 4; j++) {
        bvA[j] = (cA + j < N) ? bias[cA + j] : 0.f;
        bvB[j] = (cB + j < N) ? bias[cB + j] : 0.f;
    }

    #pragma unroll
    for (int i = 0; i < 8; i++) {
        const int m = m0 + mg * 8 + i;
        float vA[4], vB[4];
        #pragma unroll
        for (int j = 0; j < 4; j++) {
            float c = acc[i][j] + bvA[j];
            if (RELU) c = fmaxf(c, 0.f);
            vA[j] = c;
            if (STATS && cA + j < N) { colSum[j] += c; colSq[j] += c * c; }
            c = acc[i][4 + j] + bvB[j];
            if (RELU) c = fmaxf(c, 0.f);
            vB[j] = c;
            if (STATS && cB + j < N) { colSum[4 + j] += c; colSq[4 + j] += c * c; }
        }
        const size_t rowBase = (size_t)m * N;
        if (wVec && cA + 4 <= N && (rowBase + cA + 4) * 4 <= cBudget) {
            *(float4*)(C + rowBase + cA) = make_float4(vA[0],vA[1],vA[2],vA[3]);
        } else {
            #pragma unroll
            for (int j = 0; j < 4; j++)
                if (cA + j < N && (rowBase + cA + j + 1) * 4 <= cBudget)
                    C[rowBase + cA + j] = vA[j];
        }
        if (wVec && cB + 4 <= N && (rowBase + cB + 4) * 4 <= cBudget) {
            *(float4*)(C + rowBase + cB) = make_float4(vB[0],vB[1],vB[2],vB[3]);
        } else {
            #pragma unroll
            for (int j = 0; j < 4; j++)
                if (cB + j < N && (rowBase + cB + j + 1) * 4 <= cBudget)
                    C[rowBase + cB + j] = vB[j];
        }
    }

    if (STATS) {
        if (tid < BN) { sSum[tid] = 0.f; sSq[tid] = 0.f; }
        __syncthreads();
        #pragma unroll
        for (int j = 0; j < 4; j++) {
            atomicAdd(&sSum[ng * 4 + j],      colSum[j]);
            atomicAdd(&sSq [ng * 4 + j],      colSq [j]);
            atomicAdd(&sSum[32 + ng * 4 + j], colSum[4 + j]);
            atomicAdd(&sSq [32 + ng * 4 + j], colSq [4 + j]);
        }
        __syncthreads();
        if (tid < BN) {
            int n = n0 + tid;
            if (n < N) {
                atomicAdd(&g_sum[statOff + n], sSum[tid]);
                atomicAdd(&g_sq [statOff + n], sSq [tid]);
            }
        }
    }
}

// ---------------- small scalar GEMM (N=63 final projection) ----------------
template<bool RELU, bool STATS, bool NORM>
__global__ void __launch_bounds__(256, 4)
sgemm_kernel(const float* __restrict__ Aext, int Asel,
             const float* __restrict__ W,
             const float* __restrict__ bias,
             int normOff,
             float* __restrict__ Cext, int Csel,
             int statOff,
             int N, int K)
{
    const int BM = 128, BN = 64, BK = 8, TM = 8, TN = 4;
    __shared__ float As[BK][BM];
    __shared__ float Ws[BK][BN];

    const float* A = (Asel >= 0) ? sel_buf(Asel) : Aext;
    float*       C = (Csel >= 0) ? sel_buf(Csel) : Cext;

    const int m0  = blockIdx.y * BM;
    const int n0  = blockIdx.x * BN;
    const int tid = threadIdx.x;
    const int tx  = tid & 15;
    const int ty  = tid >> 4;

    float acc[TM][TN];
    #pragma unroll
    for (int i = 0; i < TM; i++)
        #pragma unroll
        for (int j = 0; j < TN; j++) acc[i][j] = 0.f;

    for (int k0 = 0; k0 < K; k0 += BK) {
        #pragma unroll
        for (int i = 0; i < 4; i++) {
            int idx = tid + i * 256;
            int mm  = idx >> 3;
            int kk  = idx & 7;
            int k   = k0 + kk;
            float v = 0.f;
            if (k < K) {
                v = A[(size_t)(m0 + mm) * K + k];
                if (NORM) v = fmaf(v, g_scale[normOff + k], g_shift[normOff + k]);
            }
            As[kk][mm] = v;
        }
        #pragma unroll
        for (int i = 0; i < 2; i++) {
            int idx = tid + i * 256;
            int kk  = idx >> 6;
            int nn  = idx & 63;
            int k   = k0 + kk, n = n0 + nn;
            Ws[kk][nn] = (k < K && n < N) ? W[(size_t)k * N + n] : 0.f;
        }
        __syncthreads();
        #pragma unroll
        for (int kk = 0; kk < BK; kk++) {
            float ar[TM], br[TN];
            #pragma unroll
            for (int i = 0; i < TM; i++) ar[i] = As[kk][ty * TM + i];
            #pragma unroll
            for (int j = 0; j < TN; j++) br[j] = Ws[kk][tx * TN + j];
            #pragma unroll
            for (int i = 0; i < TM; i++)
                #pragma unroll
                for (int j = 0; j < TN; j++)
                    acc[i][j] = fmaf(ar[i], br[j], acc[i][j]);
        }
        __syncthreads();
    }

    #pragma unroll
    for (int j = 0; j < TN; j++) {
        int n = n0 + tx * TN + j;
        if (n < N) {
            float bv = bias[n];
            #pragma unroll
            for (int i = 0; i < TM; i++) {
                float c = acc[i][j] + bv;
                if (RELU) c = fmaxf(c, 0.f);
                C[(size_t)(m0 + ty * TM + i) * N + n] = c;
            }
        }
    }
}

// ---------------- Toeplitz epilogue (REAL parts only, f32 output) -----------
__global__ void __launch_bounds__(256)
toeplitz_real_kernel(float* __restrict__ out,
                     size_t offB, size_t offC, size_t budgetElems)
{
    __shared__ float sre[8][32];
    const int warp = threadIdx.x >> 5;
    const int lane = threadIdx.x & 31;
    const int row  = blockIdx.x * 8 + warp;

    const float* ar = g_a + (size_t)row * 63;
    float v0 = ar[lane];
    float a0 = fminf(expf(__shfl_sync(0xffffffffu, v0, 0)), 500.f);

    float re = (lane == 0) ? a0 : (0.022f * a0 * tanhf(v0));
    sre[warp][lane] = re;
    __syncwarp();

    const size_t rbase = (size_t)row * 1024 + lane;
    #pragma unroll
    for (int i = 0; i < 32; i++) {
        int d = i - lane;
        float b = (d >= 0) ? sre[warp][d]      : 0.f;
        float c = (d >= 1) ? sre[warp][32 - d] : 0.f;
        size_t ib = offB + rbase + (size_t)i * 32;
        size_t ic = offC + rbase + (size_t)i * 32;
        if (ib < budgetElems) out[ib] = b;
        if (ic < budgetElems) out[ic] = c;
    }
}

// ---------------- launch -----------------------------------------------------
extern "C" void kernel_launch(void* const* d_in, const int* in_sizes, int n_in,
                              void* d_out, int out_size)
{
    if (n_in < 17) return;

    const float* z   = (const float*)d_in[0];
    const float* W1  = (const float*)d_in[1];
    const float* b1  = (const float*)d_in[2];
    const float* g1  = (const float*)d_in[3];
    const float* be1 = (const float*)d_in[4];
    const float* W2  = (const float*)d_in[5];
    const float* b2  = (const float*)d_in[6];
    const float* g2  = (const float*)d_in[7];
    const float* be2 = (const float*)d_in[8];
    const float* W3  = (const float*)d_in[9];
    const float* b3  = (const float*)d_in[10];
    const float* Wa1 = (const float*)d_in[11];
    const float* ba1 = (const float*)d_in[12];
    const float* ga  = (const float*)d_in[13];
    const float* bea = (const float*)d_in[14];
    const float* Wa2 = (const float*)d_in[15];
    const float* ba2 = (const float*)d_in[16];

    long long Braw = (long long)in_sizes[0] / 24;
    if (Braw > BATCH) Braw = BATCH;
    Braw -= (Braw % 128);
    if (Braw <= 0) return;
    const int B = (int)Braw;
    const long long LB = (long long)B;

    float* out = (float*)d_out;
    const float invB = 1.0f / (float)B;
    const size_t budgetBytes = (size_t)out_size * 4;
    const size_t budgetElems = (size_t)out_size;
    const size_t BIG = (size_t)-1;
    const int mB = B / 128;

    // 0. zero stat accumulators
    zero_stats_kernel<<<4, 256>>>();

    // 1. h = relu(z @ W1 + b1) -> g_h, stats @0        (K=24, N=300)
    fgemm_kernel<true, true, false><<<dim3(5, mB), 128>>>(
        z, -1, W1, b1, 0, nullptr, 0, BIG, 0, 300, 24);

    // 2. finalize BN1
    finalize_stats_kernel<<<2, 256>>>(g1, be1, 0, 300, invB);

    // 3. m = relu(BN(h) @ W2 + b2) -> g_m, stats @300  (K=300, N=400)
    fgemm_kernel<true, true, true><<<dim3(7, mB), 128>>>(
        nullptr, 0, W2, b2, 0, nullptr, 1, BIG, 300, 400, 300);

    // 4. ap = relu(BN(h) @ Wa1 + ba1) -> g_ap, stats @700 (K=300, N=150)
    fgemm_kernel<true, true, true><<<dim3(3, mB), 128>>>(
        nullptr, 0, Wa1, ba1, 0, nullptr, 2, BIG, 700, 150, 300);

    // 5. finalize BN2, BNa
    finalize_stats_kernel<<<2, 256>>>(g2, be2, 300, 400, invB);
    finalize_stats_kernel<<<1, 256>>>(ga, bea, 700, 150, invB);

    // 6. mu_out = BN(m) @ W3 + b3 -> out[0 .. B*1024)  (K=400, N=1024)
    fgemm_kernel<false, false, true><<<dim3(16, mB), 128>>>(
        nullptr, 1, W3, b3, 300, out, -1, budgetBytes, 0, 1024, 400);

    // 7. a = BN(ap) @ Wa2 + ba2 -> g_a   (K=150, N=63 -> scalar kernel)
    sgemm_kernel<false, false, true><<<dim3(1, mB), 256>>>(
        nullptr, 2, Wa2, ba2, 700, nullptr, 3, 0, 63, 150);

    // 8. Toeplitz real parts
    toeplitz_real_kernel<<<B / 8, 256>>>(out, (size_t)LB * 1024,
                                         (size_t)LB * 2048, budgetElems);
}

// round 8
// speedup vs baseline: 1.6899x; 1.0010x over previous
#include <cuda_runtime.h>
#include <cuda_bf16.h>
#include <math.h>

#define BATCH   32768
#define EPS     1e-5f

// ---------------- scratch (device globals; no cudaMalloc allowed) ----------
__device__ float g_h [ (size_t)BATCH * 300 ];
__device__ float g_m [ (size_t)BATCH * 400 ];
__device__ float g_ap[ (size_t)BATCH * 150 ];
__device__ float g_a [ (size_t)BATCH * 63  ];

// stats: layer1 @0 (300), layer2 @300 (400), layerA @700 (150)
#define STATS_TOTAL 860
__device__ float g_sum  [STATS_TOTAL];
__device__ float g_sq   [STATS_TOTAL];
__device__ float g_scale[STATS_TOTAL];
__device__ float g_shift[STATS_TOTAL];

__device__ __forceinline__ float* sel_buf(int s) {
    switch (s) {
        case 0: return g_h;
        case 1: return g_m;
        case 2: return g_ap;
        case 3: return g_a;
    }
    return nullptr;
}

__global__ void zero_stats_kernel() {
    int i = blockIdx.x * blockDim.x + threadIdx.x;
    if (i < STATS_TOTAL) { g_sum[i] = 0.f; g_sq[i] = 0.f; }
}

__global__ void finalize_stats_kernel(const float* __restrict__ g,
                                      const float* __restrict__ be,
                                      int off, int n, float invB) {
    int i = blockIdx.x * blockDim.x + threadIdx.x;
    if (i < n) {
        float mean = g_sum[off + i] * invB;
        float var  = g_sq [off + i] * invB - mean * mean;
        float s    = g[i] * rsqrtf(var + EPS);
        g_scale[off + i] = s;
        g_shift[off + i] = be[i] - mean * s;
    }
}

// ---------------- tile loaders (global -> registers) ------------------------
template<bool NORM>
__device__ __forceinline__ void load_A_regs(const float* __restrict__ Arow,
                                            int k0, int K, int normOff,
                                            float av[16])
{
    if (k0 + 16 <= K) {
        const float4* p = (const float4*)(Arow + k0);
        float4 t0 = p[0], t1 = p[1], t2 = p[2], t3 = p[3];
        av[0]=t0.x; av[1]=t0.y; av[2]=t0.z; av[3]=t0.w;
        av[4]=t1.x; av[5]=t1.y; av[6]=t1.z; av[7]=t1.w;
        av[8]=t2.x; av[9]=t2.y; av[10]=t2.z; av[11]=t2.w;
        av[12]=t3.x; av[13]=t3.y; av[14]=t3.z; av[15]=t3.w;
        if (NORM) {
            #pragma unroll
            for (int q = 0; q < 16; q++)
                av[q] = fmaf(av[q], g_scale[normOff + k0 + q],
                                    g_shift[normOff + k0 + q]);
        }
    } else {
        #pragma unroll
        for (int q = 0; q < 16; q++) {
            int k = k0 + q;
            float v = 0.f;
            if (k < K) {
                v = Arow[k];
                if (NORM) v = fmaf(v, g_scale[normOff + k], g_shift[normOff + k]);
            }
            av[q] = v;
        }
    }
}

__device__ __forceinline__ void load_W_regs(const float* __restrict__ W,
                                            int k0, int wk, int n0, int wn,
                                            int N, int K, bool wVec,
                                            float4& w0, float4& w1)
{
    w0 = make_float4(0.f,0.f,0.f,0.f);
    w1 = w0;
    int k = k0 + wk;
    int n = n0 + wn;
    if (k < K) {
        const float* wr = W + (size_t)k * N;
        if (wVec && n + 8 <= N) {
            w0 = *(const float4*)(wr + n);
            w1 = *(const float4*)(wr + n + 4);
        } else {
            float t[8];
            #pragma unroll
            for (int j = 0; j < 8; j++)
                t[j] = (n + j < N) ? wr[n + j] : 0.f;
            w0 = make_float4(t[0],t[1],t[2],t[3]);
            w1 = make_float4(t[4],t[5],t[6],t[7]);
        }
    }
}

// ============================================================================
// Double-buffered fp32 GEMM: BM=128, BN=64, BK=16, 128 threads, 8x8/thread.
// One __syncthreads per K-tile; next tile's global loads overlap compute.
// ============================================================================
template<bool RELU, bool STATS, bool NORM>
__global__ void __launch_bounds__(128)
fgemm_kernel(const float* __restrict__ Aext, int Asel,
             const float* __restrict__ W,
             const float* __restrict__ bias,
             int normOff,
             float* __restrict__ Cext, int Csel, size_t cBudget,
             int statOff,
             int N, int K)
{
    const int BM = 128, BN = 64, BK = 16;
    __shared__ __align__(16) float As[2][BK][BM];
    __shared__ __align__(16) float Ws[2][BK][BN];
    __shared__ float sSum[BN], sSq[BN];

    const float* A = (Asel >= 0) ? sel_buf(Asel) : Aext;
    float*       C = (Csel >= 0) ? sel_buf(Csel) : Cext;

    const int m0  = blockIdx.y * BM;
    const int n0  = blockIdx.x * BN;
    const int tid = threadIdx.x;
    const int mg  = tid >> 3;        // 0..15
    const int ng  = tid & 7;         // 0..7
    const int wk  = tid >> 3;        // W row within tile
    const int wn  = (tid & 7) * 8;   // W col offset

    const float* Arow = A + (size_t)(m0 + tid) * K;
    const bool wVec = ((N & 3) == 0);

    float acc[8][8];
    #pragma unroll
    for (int i = 0; i < 8; i++)
        #pragma unroll
        for (int j = 0; j < 8; j++) acc[i][j] = 0.f;

    const int nTiles = (K + BK - 1) / BK;

    // prologue: load tile 0 into buffer 0
    float av[16];
    float4 w0, w1;
    load_A_regs<NORM>(Arow, 0, K, normOff, av);
    load_W_regs(W, 0, wk, n0, wn, N, K, wVec, w0, w1);
    #pragma unroll
    for (int q = 0; q < 16; q++) As[0][q][tid] = av[q];
    *(float4*)&Ws[0][wk][wn]     = w0;
    *(float4*)&Ws[0][wk][wn + 4] = w1;
    __syncthreads();

    for (int t = 0; t < nTiles; t++) {
        const int buf = t & 1;
        const bool more = (t + 1 < nTiles);

        // prefetch next tile into registers (LDG overlaps compute below)
        if (more) {
            load_A_regs<NORM>(Arow, (t + 1) * BK, K, normOff, av);
            load_W_regs(W, (t + 1) * BK, wk, n0, wn, N, K, wVec, w0, w1);
        }

        // compute on current buffer: 16 k-steps, 64 FFMA + 4 LDS.128 each
        #pragma unroll
        for (int kk = 0; kk < BK; kk++) {
            float4 a0 = *(const float4*)&As[buf][kk][mg * 8];
            float4 a1 = *(const float4*)&As[buf][kk][mg * 8 + 4];
            float4 b0 = *(const float4*)&Ws[buf][kk][ng * 4];
            float4 b1 = *(const float4*)&Ws[buf][kk][32 + ng * 4];
            float ar[8] = {a0.x,a0.y,a0.z,a0.w,a1.x,a1.y,a1.z,a1.w};
            float br[8] = {b0.x,b0.y,b0.z,b0.w,b1.x,b1.y,b1.z,b1.w};
            #pragma unroll
            for (int i = 0; i < 8; i++)
                #pragma unroll
                for (int j = 0; j < 8; j++)
                    acc[i][j] = fmaf(ar[i], br[j], acc[i][j]);
        }

        if (more) {
            const int nb = buf ^ 1;
            #pragma unroll
            for (int q = 0; q < 16; q++) As[nb][q][tid] = av[q];
            *(float4*)&Ws[nb][wk][wn]     = w0;
            *(float4*)&Ws[nb][wk][wn + 4] = w1;
            __syncthreads();
        }
    }

    // ---- epilogue: bias, relu, store (vectorized), stats --------------------
    float colSum[8], colSq[8];
    #pragma unroll
    for (int j = 0; j < 8; j++) { colSum[j] = 0.f; colSq[j] = 0.f; }

    const int cA = n0 + ng * 4;
    const int cB = n0 + 32 + ng * 4;
    float bvA[4], bvB[4];
    #pragma unroll
    for (int j = 0; j < 4; j++) {
        bvA[j] = (cA + j < N) ? bias[cA + j] : 0.f;
        bvB[j] = (cB + j < N) ? bias[cB + j] : 0.f;
    }

    #pragma unroll
    for (int i = 0; i < 8; i++) {
        const int m = m0 + mg * 8 + i;
        float vA[4], vB[4];
        #pragma unroll
        for (int j = 0; j < 4; j++) {
            float c = acc[i][j] + bvA[j];
            if (RELU) c = fmaxf(c, 0.f);
            vA[j] = c;
            if (STATS && cA + j < N) { colSum[j] += c; colSq[j] += c * c; }
            c = acc[i][4 + j] + bvB[j];
            if (RELU) c = fmaxf(c, 0.f);
            vB[j] = c;
            if (STATS && cB + j < N) { colSum[4 + j] += c; colSq[4 + j] += c * c; }
        }
        const size_t rowBase = (size_t)m * N;
        if (wVec && cA + 4 <= N && (rowBase + cA + 4) * 4 <= cBudget) {
            *(float4*)(C + rowBase + cA) = make_float4(vA[0],vA[1],vA[2],vA[3]);
        } else {
            #pragma unroll
            for (int j = 0; j < 4; j++)
                if (cA + j < N && (rowBase + cA + j + 1) * 4 <= cBudget)
                    C[rowBase + cA + j] = vA[j];
        }
        if (wVec && cB + 4 <= N && (rowBase + cB + 4) * 4 <= cBudget) {
            *(float4*)(C + rowBase + cB) = make_float4(vB[0],vB[1],vB[2],vB[3]);
        } else {
            #pragma unroll
            for (int j = 0; j < 4; j++)
                if (cB + j < N && (rowBase + cB + j + 1) * 4 <= cBudget)
                    C[rowBase + cB + j] = vB[j];
        }
    }

    if (STATS) {
        if (tid < BN) { sSum[tid] = 0.f; sSq[tid] = 0.f; }
        __syncthreads();
        #pragma unroll
        for (int j = 0; j < 4; j++) {
            atomicAdd(&sSum[ng * 4 + j],      colSum[j]);
            atomicAdd(&sSq [ng * 4 + j],      colSq [j]);
            atomicAdd(&sSum[32 + ng * 4 + j], colSum[4 + j]);
            atomicAdd(&sSq [32 + ng * 4 + j], colSq [4 + j]);
        }
        __syncthreads();
        if (tid < BN) {
            int n = n0 + tid;
            if (n < N) {
                atomicAdd(&g_sum[statOff + n], sSum[tid]);
                atomicAdd(&g_sq [statOff + n], sSq [tid]);
            }
        }
    }
}

// ---------------- small scalar GEMM (N=63 final projection) ----------------
template<bool RELU, bool STATS, bool NORM>
__global__ void __launch_bounds__(256, 4)
sgemm_kernel(const float* __restrict__ Aext, int Asel,
             const float* __restrict__ W,
             const float* __restrict__ bias,
             int normOff,
             float* __restrict__ Cext, int Csel,
             int statOff,
             int N, int K)
{
    const int BM = 128, BN = 64, BK = 8, TM = 8, TN = 4;
    __shared__ float As[BK][BM];
    __shared__ float Ws[BK][BN];

    const float* A = (Asel >= 0) ? sel_buf(Asel) : Aext;
    float*       C = (Csel >= 0) ? sel_buf(Csel) : Cext;

    const int m0  = blockIdx.y * BM;
    const int n0  = blockIdx.x * BN;
    const int tid = threadIdx.x;
    const int tx  = tid & 15;
    const int ty  = tid >> 4;

    float acc[TM][TN];
    #pragma unroll
    for (int i = 0; i < TM; i++)
        #pragma unroll
        for (int j = 0; j < TN; j++) acc[i][j] = 0.f;

    for (int k0 = 0; k0 < K; k0 += BK) {
        #pragma unroll
        for (int i = 0; i < 4; i++) {
            int idx = tid + i * 256;
            int mm  = idx >> 3;
            int kk  = idx & 7;
            int k   = k0 + kk;
            float v = 0.f;
            if (k < K) {
                v = A[(size_t)(m0 + mm) * K + k];
                if (NORM) v = fmaf(v, g_scale[normOff + k], g_shift[normOff + k]);
            }
            As[kk][mm] = v;
        }
        #pragma unroll
        for (int i = 0; i < 2; i++) {
            int idx = tid + i * 256;
            int kk  = idx >> 6;
            int nn  = idx & 63;
            int k   = k0 + kk, n = n0 + nn;
            Ws[kk][nn] = (k < K && n < N) ? W[(size_t)k * N + n] : 0.f;
        }
        __syncthreads();
        #pragma unroll
        for (int kk = 0; kk < BK; kk++) {
            float ar[TM], br[TN];
            #pragma unroll
            for (int i = 0; i < TM; i++) ar[i] = As[kk][ty * TM + i];
            #pragma unroll
            for (int j = 0; j < TN; j++) br[j] = Ws[kk][tx * TN + j];
            #pragma unroll
            for (int i = 0; i < TM; i++)
                #pragma unroll
                for (int j = 0; j < TN; j++)
                    acc[i][j] = fmaf(ar[i], br[j], acc[i][j]);
        }
        __syncthreads();
    }

    #pragma unroll
    for (int j = 0; j < TN; j++) {
        int n = n0 + tx * TN + j;
        if (n < N) {
            float bv = bias[n];
            #pragma unroll
            for (int i = 0; i < TM; i++) {
                float c = acc[i][j] + bv;
                if (RELU) c = fmaxf(c, 0.f);
                C[(size_t)(m0 + ty * TM + i) * N + n] = c;
            }
        }
    }
}

// ---------------- Toeplitz epilogue (REAL parts only, f32 output) -----------
__global__ void __launch_bounds__(256)
toeplitz_real_kernel(float* __restrict__ out,
                     size_t offB, size_t offC, size_t budgetElems)
{
    __shared__ float sre[8][32];
    const int warp = threadIdx.x >> 5;
    const int lane = threadIdx.x & 31;
    const int row  = blockIdx.x * 8 + warp;

    const float* ar = g_a + (size_t)row * 63;
    float v0 = ar[lane];
    float a0 = fminf(expf(__shfl_sync(0xffffffffu, v0, 0)), 500.f);

    float re = (lane == 0) ? a0 : (0.022f * a0 * tanhf(v0));
    sre[warp][lane] = re;
    __syncwarp();

    const size_t rbase = (size_t)row * 1024 + lane;
    #pragma unroll
    for (int i = 0; i < 32; i++) {
        int d = i - lane;
        float b = (d >= 0) ? sre[warp][d]      : 0.f;
        float c = (d >= 1) ? sre[warp][32 - d] : 0.f;
        size_t ib = offB + rbase + (size_t)i * 32;
        size_t ic = offC + rbase + (size_t)i * 32;
        if (ib < budgetElems) out[ib] = b;
        if (ic < budgetElems) out[ic] = c;
    }
}

// ---------------- launch -----------------------------------------------------
extern "C" void kernel_launch(void* const* d_in, const int* in_sizes, int n_in,
                              void* d_out, int out_size)
{
    if (n_in < 17) return;

    const float* z   = (const float*)d_in[0];
    const float* W1  = (const float*)d_in[1];
    const float* b1  = (const float*)d_in[2];
    const float* g1  = (const float*)d_in[3];
    const float* be1 = (const float*)d_in[4];
    const float* W2  = (const float*)d_in[5];
    const float* b2  = (const float*)d_in[6];
    const float* g2  = (const float*)d_in[7];
    const float* be2 = (const float*)d_in[8];
    const float* W3  = (const float*)d_in[9];
    const float* b3  = (const float*)d_in[10];
    const float* Wa1 = (const float*)d_in[11];
    const float* ba1 = (const float*)d_in[12];
    const float* ga  = (const float*)d_in[13];
    const float* bea = (const float*)d_in[14];
    const float* Wa2 = (const float*)d_in[15];
    const float* ba2 = (const float*)d_in[16];

    long long Braw = (long long)in_sizes[0] / 24;
    if (Braw > BATCH) Braw = BATCH;
    Braw -= (Braw % 128);
    if (Braw <= 0) return;
    const int B = (int)Braw;
    const long long LB = (long long)B;

    float* out = (float*)d_out;
    const float invB = 1.0f / (float)B;
    const size_t budgetBytes = (size_t)out_size * 4;
    const size_t budgetElems = (size_t)out_size;
    const size_t BIG = (size_t)-1;
    const int mB = B / 128;

    // 0. zero stat accumulators
    zero_stats_kernel<<<4, 256>>>();

    // 1. h = relu(z @ W1 + b1) -> g_h, stats @0        (K=24, N=300)
    fgemm_kernel<true, true, false><<<dim3(5, mB), 128>>>(
        z, -1, W1, b1, 0, nullptr, 0, BIG, 0, 300, 24);

    // 2. finalize BN1
    finalize_stats_kernel<<<2, 256>>>(g1, be1, 0, 300, invB);

    // 3. m = relu(BN(h) @ W2 + b2) -> g_m, stats @300  (K=300, N=400)
    fgemm_kernel<true, true, true><<<dim3(7, mB), 128>>>(
        nullptr, 0, W2, b2, 0, nullptr, 1, BIG, 300, 400, 300);

    // 4. ap = relu(BN(h) @ Wa1 + ba1) -> g_ap, stats @700 (K=300, N=150)
    fgemm_kernel<true, true, true><<<dim3(3, mB), 128>>>(
        nullptr, 0, Wa1, ba1, 0, nullptr, 2, BIG, 700, 150, 300);

    // 5. finalize BN2, BNa
    finalize_stats_kernel<<<2, 256>>>(g2, be2, 300, 400, invB);
    finalize_stats_kernel<<<1, 256>>>(ga, bea, 700, 150, invB);

    // 6. mu_out = BN(m) @ W3 + b3 -> out[0 .. B*1024)  (K=400, N=1024)
    fgemm_kernel<false, false, true><<<dim3(16, mB), 128>>>(
        nullptr, 1, W3, b3, 300, out, -1, budgetBytes, 0, 1024, 400);

    // 7. a = BN(ap) @ Wa2 + ba2 -> g_a   (K=150, N=63 -> scalar kernel)
    sgemm_kernel<false, false, true><<<dim3(1, mB), 256>>>(
        nullptr, 2, Wa2, ba2, 700, nullptr, 3, 0, 63, 150);

    // 8. Toeplitz real parts
    toeplitz_real_kernel<<<B / 8, 256>>>(out, (size_t)LB * 1024,
                                         (size_t)LB * 2048, budgetElems);
}

// round 9
// speedup vs baseline: 1.8115x; 1.0720x over previous
#include <cuda_runtime.h>
#include <cuda_bf16.h>
#include <math.h>

#define BATCH   32768
#define EPS     1e-5f

// ---------------- scratch (device globals; no cudaMalloc allowed) ----------
__device__ float g_h [ (size_t)BATCH * 300 ];
__device__ float g_m [ (size_t)BATCH * 400 ];
__device__ float g_ap[ (size_t)BATCH * 150 ];
__device__ float g_a [ (size_t)BATCH * 63  ];

// stats: layer1 @0 (300), layer2 @300 (400), layerA @700 (150)
#define STATS_TOTAL 860
__device__ float g_sum  [STATS_TOTAL];
__device__ float g_sq   [STATS_TOTAL];
__device__ float g_scale[STATS_TOTAL];
__device__ float g_shift[STATS_TOTAL];

__device__ __forceinline__ float* sel_buf(int s) {
    switch (s) {
        case 0: return g_h;
        case 1: return g_m;
        case 2: return g_ap;
        case 3: return g_a;
    }
    return nullptr;
}

__global__ void zero_stats_kernel() {
    int i = blockIdx.x * blockDim.x + threadIdx.x;
    if (i < STATS_TOTAL) { g_sum[i] = 0.f; g_sq[i] = 0.f; }
}

__global__ void finalize_stats_kernel(const float* __restrict__ g,
                                      const float* __restrict__ be,
                                      int off, int n, float invB) {
    int i = blockIdx.x * blockDim.x + threadIdx.x;
    if (i < n) {
        float mean = g_sum[off + i] * invB;
        float var  = g_sq [off + i] * invB - mean * mean;
        float s    = g[i] * rsqrtf(var + EPS);
        g_scale[off + i] = s;
        g_shift[off + i] = be[i] - mean * s;
    }
}

// ---------------- packed fp32x2 primitives (FFMA2 — PTX-only on sm_103a) ---
typedef unsigned long long u64;

__device__ __forceinline__ u64 pack_dup(float x) {
    u64 r;
    asm("mov.b64 %0, {%1, %1};" : "=l"(r) : "r"(__float_as_uint(x)));
    return r;
}
__device__ __forceinline__ void unpack2(u64 v, float& x, float& y) {
    unsigned int a, b;
    asm("mov.b64 {%0, %1}, %2;" : "=r"(a), "=r"(b) : "l"(v));
    x = __uint_as_float(a);
    y = __uint_as_float(b);
}
__device__ __forceinline__ void fma2(u64& d, u64 a, u64 b) {
    asm("fma.rn.f32x2 %0, %1, %2, %3;" : "=l"(d) : "l"(a), "l"(b), "l"(d));
}

// ---------------- tile loaders (global -> registers) ------------------------
template<bool NORM>
__device__ __forceinline__ void load_A_regs(const float* __restrict__ Arow,
                                            int k0, int K, int normOff,
                                            float av[16])
{
    if (k0 + 16 <= K) {
        const float4* p = (const float4*)(Arow + k0);
        float4 t0 = p[0], t1 = p[1], t2 = p[2], t3 = p[3];
        av[0]=t0.x; av[1]=t0.y; av[2]=t0.z; av[3]=t0.w;
        av[4]=t1.x; av[5]=t1.y; av[6]=t1.z; av[7]=t1.w;
        av[8]=t2.x; av[9]=t2.y; av[10]=t2.z; av[11]=t2.w;
        av[12]=t3.x; av[13]=t3.y; av[14]=t3.z; av[15]=t3.w;
        if (NORM) {
            #pragma unroll
            for (int q = 0; q < 16; q++)
                av[q] = fmaf(av[q], g_scale[normOff + k0 + q],
                                    g_shift[normOff + k0 + q]);
        }
    } else {
        #pragma unroll
        for (int q = 0; q < 16; q++) {
            int k = k0 + q;
            float v = 0.f;
            if (k < K) {
                v = Arow[k];
                if (NORM) v = fmaf(v, g_scale[normOff + k], g_shift[normOff + k]);
            }
            av[q] = v;
        }
    }
}

__device__ __forceinline__ void load_W_regs(const float* __restrict__ W,
                                            int k0, int wk, int n0, int wn,
                                            int N, int K, bool wVec,
                                            float4& w0, float4& w1)
{
    w0 = make_float4(0.f,0.f,0.f,0.f);
    w1 = w0;
    int k = k0 + wk;
    int n = n0 + wn;
    if (k < K) {
        const float* wr = W + (size_t)k * N;
        if (wVec && n + 8 <= N) {
            w0 = *(const float4*)(wr + n);
            w1 = *(const float4*)(wr + n + 4);
        } else {
            float t[8];
            #pragma unroll
            for (int j = 0; j < 8; j++)
                t[j] = (n + j < N) ? wr[n + j] : 0.f;
            w0 = make_float4(t[0],t[1],t[2],t[3]);
            w1 = make_float4(t[4],t[5],t[6],t[7]);
        }
    }
}

// ============================================================================
// FFMA2 GEMM: BM=128, BN=64, BK=16, 128 threads, 8x8/thread via packed f32x2.
// Double-buffered smem; conflict-free LDS.128.
// ============================================================================
template<bool RELU, bool STATS, bool NORM>
__global__ void __launch_bounds__(128)
fgemm_kernel(const float* __restrict__ Aext, int Asel,
             const float* __restrict__ W,
             const float* __restrict__ bias,
             int normOff,
             float* __restrict__ Cext, int Csel, size_t cBudget,
             int statOff,
             int N, int K)
{
    const int BM = 128, BN = 64, BK = 16;
    __shared__ __align__(16) float As[2][BK][BM];
    __shared__ __align__(16) float Ws[2][BK][BN];
    __shared__ float sSum[BN], sSq[BN];

    const float* A = (Asel >= 0) ? sel_buf(Asel) : Aext;
    float*       C = (Csel >= 0) ? sel_buf(Csel) : Cext;

    const int m0  = blockIdx.y * BM;
    const int n0  = blockIdx.x * BN;
    const int tid = threadIdx.x;
    const int mg  = tid >> 3;        // 0..15
    const int ng  = tid & 7;         // 0..7
    const int wk  = tid >> 3;
    const int wn  = (tid & 7) * 8;

    const float* Arow = A + (size_t)(m0 + tid) * K;
    const bool wVec = ((N & 3) == 0);

    // acc2[i][p] holds packed columns (2p, 2p+1) of the 8-wide split tile
    u64 acc2[8][4];
    #pragma unroll
    for (int i = 0; i < 8; i++)
        #pragma unroll
        for (int p = 0; p < 4; p++) acc2[i][p] = 0ull;

    const int nTiles = (K + BK - 1) / BK;

    float av[16];
    float4 w0, w1;
    load_A_regs<NORM>(Arow, 0, K, normOff, av);
    load_W_regs(W, 0, wk, n0, wn, N, K, wVec, w0, w1);
    #pragma unroll
    for (int q = 0; q < 16; q++) As[0][q][tid] = av[q];
    *(float4*)&Ws[0][wk][wn]     = w0;
    *(float4*)&Ws[0][wk][wn + 4] = w1;
    __syncthreads();

    for (int t = 0; t < nTiles; t++) {
        const int buf = t & 1;
        const bool more = (t + 1 < nTiles);

        if (more) {
            load_A_regs<NORM>(Arow, (t + 1) * BK, K, normOff, av);
            load_W_regs(W, (t + 1) * BK, wk, n0, wn, N, K, wVec, w0, w1);
        }

        // 16 k-steps: 32 FFMA2 (=64 FMA) + 8 mov.b64 + 4 LDS.128 each
        #pragma unroll
        for (int kk = 0; kk < BK; kk++) {
            float4 a0 = *(const float4*)&As[buf][kk][mg * 8];
            float4 a1 = *(const float4*)&As[buf][kk][mg * 8 + 4];
            ulonglong2 bq0 = *(const ulonglong2*)&Ws[buf][kk][ng * 4];
            ulonglong2 bq1 = *(const ulonglong2*)&Ws[buf][kk][32 + ng * 4];
            u64 bb[4] = { bq0.x, bq0.y, bq1.x, bq1.y };
            float ar[8] = {a0.x,a0.y,a0.z,a0.w,a1.x,a1.y,a1.z,a1.w};
            #pragma unroll
            for (int i = 0; i < 8; i++) {
                u64 ai = pack_dup(ar[i]);
                #pragma unroll
                for (int p = 0; p < 4; p++)
                    fma2(acc2[i][p], ai, bb[p]);
            }
        }

        if (more) {
            const int nb = buf ^ 1;
            #pragma unroll
            for (int q = 0; q < 16; q++) As[nb][q][tid] = av[q];
            *(float4*)&Ws[nb][wk][wn]     = w0;
            *(float4*)&Ws[nb][wk][wn + 4] = w1;
            __syncthreads();
        }
    }

    // ---- epilogue: unpack, bias, relu, store, stats -------------------------
    float colSum[8], colSq[8];
    #pragma unroll
    for (int j = 0; j < 8; j++) { colSum[j] = 0.f; colSq[j] = 0.f; }

    const int cA = n0 + ng * 4;        // packed pairs p=0,1
    const int cB = n0 + 32 + ng * 4;   // packed pairs p=2,3
    float bvA[4], bvB[4];
    #pragma unroll
    for (int j = 0; j < 4; j++) {
        bvA[j] = (cA + j < N) ? bias[cA + j] : 0.f;
        bvB[j] = (cB + j < N) ? bias[cB + j] : 0.f;
    }

    #pragma unroll
    for (int i = 0; i < 8; i++) {
        const int m = m0 + mg * 8 + i;
        float vA[4], vB[4];
        unpack2(acc2[i][0], vA[0], vA[1]);
        unpack2(acc2[i][1], vA[2], vA[3]);
        unpack2(acc2[i][2], vB[0], vB[1]);
        unpack2(acc2[i][3], vB[2], vB[3]);
        #pragma unroll
        for (int j = 0; j < 4; j++) {
            float c = vA[j] + bvA[j];
            if (RELU) c = fmaxf(c, 0.f);
            vA[j] = c;
            if (STATS && cA + j < N) { colSum[j] += c; colSq[j] += c * c; }
            c = vB[j] + bvB[j];
            if (RELU) c = fmaxf(c, 0.f);
            vB[j] = c;
            if (STATS && cB + j < N) { colSum[4 + j] += c; colSq[4 + j] += c * c; }
        }
        const size_t rowBase = (size_t)m * N;
        if (wVec && cA + 4 <= N && (rowBase + cA + 4) * 4 <= cBudget) {
            *(float4*)(C + rowBase + cA) = make_float4(vA[0],vA[1],vA[2],vA[3]);
        } else {
            #pragma unroll
            for (int j = 0; j < 4; j++)
                if (cA + j < N && (rowBase + cA + j + 1) * 4 <= cBudget)
                    C[rowBase + cA + j] = vA[j];
        }
        if (wVec && cB + 4 <= N && (rowBase + cB + 4) * 4 <= cBudget) {
            *(float4*)(C + rowBase + cB) = make_float4(vB[0],vB[1],vB[2],vB[3]);
        } else {
            #pragma unroll
            for (int j = 0; j < 4; j++)
                if (cB + j < N && (rowBase + cB + j + 1) * 4 <= cBudget)
                    C[rowBase + cB + j] = vB[j];
        }
    }

    if (STATS) {
        if (tid < BN) { sSum[tid] = 0.f; sSq[tid] = 0.f; }
        __syncthreads();
        #pragma unroll
        for (int j = 0; j < 4; j++) {
            atomicAdd(&sSum[ng * 4 + j],      colSum[j]);
            atomicAdd(&sSq [ng * 4 + j],      colSq [j]);
            atomicAdd(&sSum[32 + ng * 4 + j], colSum[4 + j]);
            atomicAdd(&sSq [32 + ng * 4 + j], colSq [4 + j]);
        }
        __syncthreads();
        if (tid < BN) {
            int n = n0 + tid;
            if (n < N) {
                atomicAdd(&g_sum[statOff + n], sSum[tid]);
                atomicAdd(&g_sq [statOff + n], sSq [tid]);
            }
        }
    }
}

// ---------------- small scalar GEMM (N=63 final projection) ----------------
template<bool RELU, bool STATS, bool NORM>
__global__ void __launch_bounds__(256, 4)
sgemm_kernel(const float* __restrict__ Aext, int Asel,
             const float* __restrict__ W,
             const float* __restrict__ bias,
             int normOff,
             float* __restrict__ Cext, int Csel,
             int statOff,
             int N, int K)
{
    const int BM = 128, BN = 64, BK = 8, TM = 8, TN = 4;
    __shared__ float As[BK][BM];
    __shared__ float Ws[BK][BN];

    const float* A = (Asel >= 0) ? sel_buf(Asel) : Aext;
    float*       C = (Csel >= 0) ? sel_buf(Csel) : Cext;

    const int m0  = blockIdx.y * BM;
    const int n0  = blockIdx.x * BN;
    const int tid = threadIdx.x;
    const int tx  = tid & 15;
    const int ty  = tid >> 4;

    float acc[TM][TN];
    #pragma unroll
    for (int i = 0; i < TM; i++)
        #pragma unroll
        for (int j = 0; j < TN; j++) acc[i][j] = 0.f;

    for (int k0 = 0; k0 < K; k0 += BK) {
        #pragma unroll
        for (int i = 0; i < 4; i++) {
            int idx = tid + i * 256;
            int mm  = idx >> 3;
            int kk  = idx & 7;
            int k   = k0 + kk;
            float v = 0.f;
            if (k < K) {
                v = A[(size_t)(m0 + mm) * K + k];
                if (NORM) v = fmaf(v, g_scale[normOff + k], g_shift[normOff + k]);
            }
            As[kk][mm] = v;
        }
        #pragma unroll
        for (int i = 0; i < 2; i++) {
            int idx = tid + i * 256;
            int kk  = idx >> 6;
            int nn  = idx & 63;
            int k   = k0 + kk, n = n0 + nn;
            Ws[kk][nn] = (k < K && n < N) ? W[(size_t)k * N + n] : 0.f;
        }
        __syncthreads();
        #pragma unroll
        for (int kk = 0; kk < BK; kk++) {
            float ar[TM], br[TN];
            #pragma unroll
            for (int i = 0; i < TM; i++) ar[i] = As[kk][ty * TM + i];
            #pragma unroll
            for (int j = 0; j < TN; j++) br[j] = Ws[kk][tx * TN + j];
            #pragma unroll
            for (int i = 0; i < TM; i++)
                #pragma unroll
                for (int j = 0; j < TN; j++)
                    acc[i][j] = fmaf(ar[i], br[j], acc[i][j]);
        }
        __syncthreads();
    }

    #pragma unroll
    for (int j = 0; j < TN; j++) {
        int n = n0 + tx * TN + j;
        if (n < N) {
            float bv = bias[n];
            #pragma unroll
            for (int i = 0; i < TM; i++) {
                float c = acc[i][j] + bv;
                if (RELU) c = fmaxf(c, 0.f);
                C[(size_t)(m0 + ty * TM + i) * N + n] = c;
            }
        }
    }
}

// ---------------- Toeplitz epilogue (REAL parts only, f32 output) -----------
__global__ void __launch_bounds__(256)
toeplitz_real_kernel(float* __restrict__ out,
                     size_t offB, size_t offC, size_t budgetElems)
{
    __shared__ float sre[8][32];
    const int warp = threadIdx.x >> 5;
    const int lane = threadIdx.x & 31;
    const int row  = blockIdx.x * 8 + warp;

    const float* ar = g_a + (size_t)row * 63;
    float v0 = ar[lane];
    float a0 = fminf(expf(__shfl_sync(0xffffffffu, v0, 0)), 500.f);

    float re = (lane == 0) ? a0 : (0.022f * a0 * tanhf(v0));
    sre[warp][lane] = re;
    __syncwarp();

    const size_t rbase = (size_t)row * 1024 + lane;
    #pragma unroll
    for (int i = 0; i < 32; i++) {
        int d = i - lane;
        float b = (d >= 0) ? sre[warp][d]      : 0.f;
        float c = (d >= 1) ? sre[warp][32 - d] : 0.f;
        size_t ib = offB + rbase + (size_t)i * 32;
        size_t ic = offC + rbase + (size_t)i * 32;
        if (ib < budgetElems) out[ib] = b;
        if (ic < budgetElems) out[ic] = c;
    }
}

// ---------------- launch -----------------------------------------------------
extern "C" void kernel_launch(void* const* d_in, const int* in_sizes, int n_in,
                              void* d_out, int out_size)
{
    if (n_in < 17) return;

    const float* z   = (const float*)d_in[0];
    const float* W1  = (const float*)d_in[1];
    const float* b1  = (const float*)d_in[2];
    const float* g1  = (const float*)d_in[3];
    const float* be1 = (const float*)d_in[4];
    const float* W2  = (const float*)d_in[5];
    const float* b2  = (const float*)d_in[6];
    const float* g2  = (const float*)d_in[7];
    const float* be2 = (const float*)d_in[8];
    const float* W3  = (const float*)d_in[9];
    const float* b3  = (const float*)d_in[10];
    const float* Wa1 = (const float*)d_in[11];
    const float* ba1 = (const float*)d_in[12];
    const float* ga  = (const float*)d_in[13];
    const float* bea = (const float*)d_in[14];
    const float* Wa2 = (const float*)d_in[15];
    const float* ba2 = (const float*)d_in[16];

    long long Braw = (long long)in_sizes[0] / 24;
    if (Braw > BATCH) Braw = BATCH;
    Braw -= (Braw % 128);
    if (Braw <= 0) return;
    const int B = (int)Braw;
    const long long LB = (long long)B;

    float* out = (float*)d_out;
    const float invB = 1.0f / (float)B;
    const size_t budgetBytes = (size_t)out_size * 4;
    const size_t budgetElems = (size_t)out_size;
    const size_t BIG = (size_t)-1;
    const int mB = B / 128;

    // 0. zero stat accumulators
    zero_stats_kernel<<<4, 256>>>();

    // 1. h = relu(z @ W1 + b1) -> g_h, stats @0        (K=24, N=300)
    fgemm_kernel<true, true, false><<<dim3(5, mB), 128>>>(
        z, -1, W1, b1, 0, nullptr, 0, BIG, 0, 300, 24);

    // 2. finalize BN1
    finalize_stats_kernel<<<2, 256>>>(g1, be1, 0, 300, invB);

    // 3. m = relu(BN(h) @ W2 + b2) -> g_m, stats @300  (K=300, N=400)
    fgemm_kernel<true, true, true><<<dim3(7, mB), 128>>>(
        nullptr, 0, W2, b2, 0, nullptr, 1, BIG, 300, 400, 300);

    // 4. ap = relu(BN(h) @ Wa1 + ba1) -> g_ap, stats @700 (K=300, N=150)
    fgemm_kernel<true, true, true><<<dim3(3, mB), 128>>>(
        nullptr, 0, Wa1, ba1, 0, nullptr, 2, BIG, 700, 150, 300);

    // 5. finalize BN2, BNa
    finalize_stats_kernel<<<2, 256>>>(g2, be2, 300, 400, invB);
    finalize_stats_kernel<<<1, 256>>>(ga, bea, 700, 150, invB);

    // 6. mu_out = BN(m) @ W3 + b3 -> out[0 .. B*1024)  (K=400, N=1024)
    fgemm_kernel<false, false, true><<<dim3(16, mB), 128>>>(
        nullptr, 1, W3, b3, 300, out, -1, budgetBytes, 0, 1024, 400);

    // 7. a = BN(ap) @ Wa2 + ba2 -> g_a   (K=150, N=63 -> scalar kernel)
    sgemm_kernel<false, false, true><<<dim3(1, mB), 256>>>(
        nullptr, 2, Wa2, ba2, 700, nullptr, 3, 0, 63, 150);

    // 8. Toeplitz real parts
    toeplitz_real_kernel<<<B / 8, 256>>>(out, (size_t)LB * 1024,
                                         (size_t)LB * 2048, budgetElems);
}